// round 12
// baseline (speedup 1.0000x reference)
#include <cuda_runtime.h>
#include <cuda_fp16.h>
#include <math.h>
#include <stdint.h>

#define BB 2
#define LL 1024
#define HH 8
#define DD 64
#define SS 10
#define T2 20      // 2S
#define RR 128
#define KTOT 1280  // DD*T2
#define KC 64      // K per chunk
#define NCH 20     // KTOT/KC
#define MT 64      // M tile (l) per CTA

#define TSZA 8192            // 64x64 fp16 tile (128B rows, SW128)
#define TSZB 16384           // 128x64 fp16 tile
#define OFF_AQ 0
#define OFF_AK (1*TSZA)
#define OFF_BQ (2*TSZA)
#define OFF_BK (2*TSZA + TSZB)
#define BUFSZ (2*TSZA + 2*TSZB)   // 48 KB
#define SMEM_BYTES (2*BUFSZ + 1024)

#define ZSCALE 64.0f
#define ZUNSCALE (1.0f/64.0f)

#define NANCH (HH*128*NCH*32)     // anchors: [h][l8][ch][pi]

static __device__ __align__(16) __half g_zTq[(size_t)BB*HH*RR*KTOT];  // offset-rotated
static __device__ __align__(16) __half g_zTk[(size_t)BB*HH*RR*KTOT];  // plain
static __device__ __align__(16) float2 g_anchor[NANCH];               // (cos,sin)(tp*l8*8)
static __device__ __align__(16) float2 g_rot[HH*NCH*32];              // (cos,sin)(tp)

// ---------------- helpers ----------------
__device__ __forceinline__ uint32_t smem_u32(const void* p) {
    uint32_t a;
    asm("{ .reg .u64 t; cvta.to.shared.u64 t, %1; cvt.u32.u64 %0, t; }" : "=r"(a) : "l"(p));
    return a;
}
__device__ __forceinline__ uint32_t swz(uint32_t b) { return b ^ ((b >> 3) & 0x70); }
__device__ __forceinline__ uint32_t h2(float x, float y) {
    __half2 h = __floats2half2_rn(x, y);
    return *(uint32_t*)&h;
}
__device__ __forceinline__ void ldsm4(uint32_t* r, uint32_t a) {
    asm volatile("ldmatrix.sync.aligned.m8n8.x4.shared.b16 {%0,%1,%2,%3}, [%4];"
        : "=r"(r[0]), "=r"(r[1]), "=r"(r[2]), "=r"(r[3]) : "r"(a));
}
__device__ __forceinline__ void mma16816(float* d, const uint32_t* a, const uint32_t* b) {
    asm volatile(
        "mma.sync.aligned.m16n8k16.row.col.f32.f16.f16.f32 "
        "{%0,%1,%2,%3}, {%4,%5,%6,%7}, {%8,%9}, {%0,%1,%2,%3};"
        : "+f"(d[0]), "+f"(d[1]), "+f"(d[2]), "+f"(d[3])
        : "r"(a[0]), "r"(a[1]), "r"(a[2]), "r"(a[3]), "r"(b[0]), "r"(b[1]));
}
__device__ __forceinline__ void cp16(uint32_t dst, const void* src) {
    asm volatile("cp.async.cg.shared.global [%0], [%1], 16;" :: "r"(dst), "l"(src) : "memory");
}

// ---------------- pre-kernel: transpose+fold AND anchor tables ----------------
// blocks [0,512): z transpose -> zTq (offset-rotated) / zTk (plain), fp16*ZSCALE
// blocks [512, 512+5120): anchor table (+ rot table at l8==0)
__global__ __launch_bounds__(128)
void spe_pre(const float* __restrict__ zg,
             const float* __restrict__ freqs,
             const float* __restrict__ offsets,
             const float* __restrict__ gains) {
    const int bid = blockIdx.x;
    const int tid = threadIdx.x;

    if (bid < 512) {
        // ---- transpose part: dp in [0,32), h in [0,8), b in [0,2) ----
        int dp = bid & 31;
        int h  = (bid >> 5) & 7;
        int b  = bid >> 8;
        __shared__ float sm[2][T2][RR + 1];
        __shared__ float cf[2][T2];
        __shared__ float cs_o[2][SS], sn_o[2][SS];
        const float scale = rsqrtf((float)(RR * DD)) * ZSCALE;

        if (tid < 2*T2) {
            int dd = tid / T2, t = tid - dd*T2;
            float x = gains[(h*DD + dp*2 + dd)*SS + (t % SS)];
            cf[dd][t] = (fmaxf(x, 0.0f) + log1pf(expf(-fabsf(x)))) * scale;
        }
        if (tid >= 64 && tid < 64 + 2*SS) {
            int u = tid - 64;
            int dd = u / SS, s = u - dd*SS;
            sincosf(offsets[(h*DD + dp*2 + dd)*SS + s], &sn_o[dd][s], &cs_o[dd][s]);
        }
        __syncthreads();

        const float* zd = zg + (((size_t)(b*HH + h)*DD + dp*2)*T2)*RR;
        for (int i = tid; i < 2*T2*RR; i += 128) {
            int dd  = i / (T2*RR);
            int rem = i - dd*(T2*RR);
            int t = rem >> 7, r = rem & 127;
            sm[dd][t][r] = zd[i] * cf[dd][t];
        }
        __syncthreads();

        const int r = tid;   // 0..127
        uint32_t pkq[20], pkk[20];
        #pragma unroll
        for (int dd = 0; dd < 2; ++dd)
            #pragma unroll
            for (int j = 0; j < 10; ++j) {
                float v0 = sm[dd][2*j][r], v1 = sm[dd][2*j + 1][r];
                pkk[dd*10 + j] = h2(v0, v1);
                float co = cs_o[dd][j], so = sn_o[dd][j];
                // zq = R(off)^T z : (co*v0 + so*v1, co*v1 - so*v0)
                pkq[dd*10 + j] = h2(co*v0 + so*v1, co*v1 - so*v0);
            }

        size_t ob = ((size_t)(b*HH + h)*RR + r)*KTOT + (size_t)dp*2*T2;  // halves
        uint4* dq = (uint4*)(g_zTq + ob);
        uint4* dk = (uint4*)(g_zTk + ob);
        #pragma unroll
        for (int v = 0; v < 5; ++v) {
            dq[v] = make_uint4(pkq[4*v], pkq[4*v+1], pkq[4*v+2], pkq[4*v+3]);
            dk[v] = make_uint4(pkk[4*v], pkk[4*v+1], pkk[4*v+2], pkk[4*v+3]);
        }
    } else {
        // ---- anchor part ----
        int idx = (bid - 512)*128 + tid;   // < NANCH
        int pi = idx & 31;
        int ch = (idx >> 5) % NCH;
        int l8 = (idx / (32*NCH)) & 127;
        int h  = idx / (32*NCH*128);
        int k  = ch*KC + 2*pi;
        int d  = k / T2;
        int s  = (k - d*T2) >> 1;
        float f = freqs[(h*DD + d)*SS + s];
        float tp = 6.28318530717958647692f * (0.5f / (1.0f + expf(-f)));
        float2 a;
        sincosf(tp * (float)(l8*8), &a.y, &a.x);
        g_anchor[((h*128 + l8)*NCH + ch)*32 + pi] = a;
        if (l8 == 0) {
            float2 r1;
            sincosf(tp, &r1.y, &r1.x);
            g_rot[(h*NCH + ch)*32 + pi] = r1;
        }
    }
}

// ---------------- main HMMA kernel ----------------
__global__ __launch_bounds__(256, 2)
void spe_mma_main(const float* __restrict__ qg,
                  const float* __restrict__ kg,
                  float* __restrict__ out) {
    extern __shared__ char smraw[];
    const uint32_t sb   = smem_u32(smraw);
    const uint32_t tb_u = (sb + 1023) & ~1023u;
    char* tb = smraw + (tb_u - sb);

    const int tid  = threadIdx.x;
    const int wid  = tid >> 5;
    const int lane = tid & 31;
    const int l0   = blockIdx.x * MT;
    const int h    = blockIdx.y;
    const int b    = blockIdx.z;

    const int mi = wid & 1;   // 2 m32 blocks
    const int ni = wid >> 1;  // 4 n32 blocks

    const __half* zTq = g_zTq + (size_t)(b*HH + h)*RR*KTOT;
    const __half* zTk = g_zTk + (size_t)(b*HH + h)*RR*KTOT;

    // ---- stageB: cp.async Bq/Bk tiles of chunk ch into buffer buf ----
    auto stageB = [&](int ch, int buf) {
        const int k0 = ch * KC;
        const uint32_t bq = tb_u + buf*BUFSZ + OFF_BQ;
        const uint32_t bk = tb_u + buf*BUFSZ + OFF_BK;
        #pragma unroll
        for (int u = 0; u < 4; ++u) {
            int idx = tid + u*256;           // 1024 units of 8 fp16
            int r   = idx >> 3;
            int kl8 = (idx & 7) * 8;
            uint32_t byte = swz((uint32_t)(r*128 + kl8*2));
            size_t gsrc = (size_t)r*KTOT + k0 + kl8;
            cp16(bq + byte, zTq + gsrc);
            cp16(bk + byte, zTk + gsrc);
        }
        asm volatile("cp.async.commit_group;" ::: "memory");
    };

    // ---- A-staging state (thread owns k-pair pi, l-strip of 8) ----
    const int pi  = tid & 31;
    const int lb  = (tid >> 5) * 8;
    const int l8g = blockIdx.x*8 + (tid >> 5);
    float st_cp, st_sp, st_c1, st_s1;
    float st_qv[8], st_kv[8];

    // prep chunk ch: anchor/rot table loads (coalesced), prefetch q/k
    auto prep = [&](int ch) {
        const int k = ch*KC + 2*pi;
        const int d = k / T2;
        float2 an = g_anchor[((h*128 + l8g)*NCH + ch)*32 + pi];
        st_cp = an.x; st_sp = an.y;
        float2 rt = g_rot[(h*NCH + ch)*32 + pi];
        st_c1 = rt.x; st_s1 = rt.y;
        const float* qp = qg + ((((size_t)b*LL + l0 + lb)*HH + h)*DD + d);
        const float* kp = kg + ((((size_t)b*LL + l0 + lb)*HH + h)*DD + d);
        #pragma unroll
        for (int i = 0; i < 8; ++i) {
            st_qv[i] = __ldg(qp + (size_t)i*(HH*DD));
            st_kv[i] = __ldg(kp + (size_t)i*(HH*DD));
        }
    };

    // stage 2 l's of the prepped chunk into buffer buf
    auto partA = [&](int buf, int i0) {
        char* tile = tb + buf*BUFSZ;
        #pragma unroll
        for (int ii = 0; ii < 2; ++ii) {
            int i = i0 + ii;
            uint32_t byte = swz((uint32_t)((lb + i)*128 + pi*4));
            *(uint32_t*)(tile + OFF_AQ + byte) = h2(st_cp*st_qv[i], st_sp*st_qv[i]);
            *(uint32_t*)(tile + OFF_AK + byte) = h2(st_cp*st_kv[i], st_sp*st_kv[i]);
            float ncp = st_cp*st_c1 - st_sp*st_s1;
            float nsp = st_sp*st_c1 + st_cp*st_s1;
            st_cp = ncp; st_sp = nsp;
        }
    };

    // accumulators: [msub 2][ntile 4][4] for q and k
    float accq[2][4][4];
    float acck[2][4][4];
    #pragma unroll
    for (int i = 0; i < 2; ++i)
        #pragma unroll
        for (int j = 0; j < 4; ++j)
            #pragma unroll
            for (int c = 0; c < 4; ++c) { accq[i][j][c] = 0.0f; acck[i][j][c] = 0.0f; }

    const uint32_t lanerow = lane & 15;
    const uint32_t lanecol = (uint32_t)(lane >> 4) * 16;

    // prologue: fill buffer 0 with chunk 0
    stageB(0, 0);
    prep(0);
    partA(0, 0); partA(0, 2); partA(0, 4); partA(0, 6);
    asm volatile("cp.async.wait_group 0;" ::: "memory");
    __syncthreads();

    #pragma unroll 1
    for (int ch = 0; ch < NCH; ++ch) {
        const int buf = ch & 1;
        const bool more = (ch + 1 < NCH);
        if (more) { stageB(ch + 1, buf ^ 1); prep(ch + 1); }

        const uint32_t base = tb_u + buf*BUFSZ;
        #pragma unroll
        for (int kk = 0; kk < 4; ++kk) {
            const uint32_t kb = kk * 32;   // 16 elems * 2B
            const uint32_t o0 = swz((ni*32 +  0 + lanerow)*128 + lanecol + kb);
            const uint32_t o1 = swz((ni*32 + 16 + lanerow)*128 + lanecol + kb);
            const uint32_t a0 = swz((mi*32 +  0 + lanerow)*128 + lanecol + kb);
            const uint32_t a1 = swz((mi*32 + 16 + lanerow)*128 + lanecol + kb);
            // --- q: Bq fragments + Aq ---
            {
                uint32_t bf[4][2];
                uint32_t t0[4], t1[4];
                ldsm4(t0, base + OFF_BQ + o0);
                ldsm4(t1, base + OFF_BQ + o1);
                bf[0][0]=t0[0]; bf[0][1]=t0[2]; bf[1][0]=t0[1]; bf[1][1]=t0[3];
                bf[2][0]=t1[0]; bf[2][1]=t1[2]; bf[3][0]=t1[1]; bf[3][1]=t1[3];
                uint32_t aq[2][4];
                ldsm4(aq[0], base + OFF_AQ + a0);
                ldsm4(aq[1], base + OFF_AQ + a1);
                #pragma unroll
                for (int s = 0; s < 2; ++s)
                    #pragma unroll
                    for (int j = 0; j < 4; ++j)
                        mma16816(accq[s][j], aq[s], bf[j]);
            }
            // --- k: Bk fragments + Ak ---
            {
                uint32_t bf[4][2];
                uint32_t t0[4], t1[4];
                ldsm4(t0, base + OFF_BK + o0);
                ldsm4(t1, base + OFF_BK + o1);
                bf[0][0]=t0[0]; bf[0][1]=t0[2]; bf[1][0]=t0[1]; bf[1][1]=t0[3];
                bf[2][0]=t1[0]; bf[2][1]=t1[2]; bf[3][0]=t1[1]; bf[3][1]=t1[3];
                uint32_t ak[2][4];
                ldsm4(ak[0], base + OFF_AK + a0);
                ldsm4(ak[1], base + OFF_AK + a1);
                #pragma unroll
                for (int s = 0; s < 2; ++s)
                    #pragma unroll
                    for (int j = 0; j < 4; ++j)
                        mma16816(acck[s][j], ak[s], bf[j]);
            }
            // --- interleaved A staging for chunk ch+1 (2 of 8 l's) ---
            if (more) partA(buf ^ 1, 2*kk);
        }

        asm volatile("cp.async.wait_group 0;" ::: "memory");
        __syncthreads();
    }

    // ---- epilogue: c-frag scatter (undo ZSCALE) ----
    const size_t khat_off = (size_t)BB * LL * HH * RR;
    #pragma unroll
    for (int s = 0; s < 2; ++s) {
        int row0 = l0 + mi*32 + s*16 + (lane >> 2);
        #pragma unroll
        for (int j = 0; j < 4; ++j) {
            int col = ni*32 + j*8 + (lane & 3)*2;
            size_t oA = (((size_t)b*LL + row0)*HH + h)*RR + col;
            size_t oB = oA + (size_t)8*HH*RR;   // row0 + 8
            *(float2*)(out + oA) = make_float2(accq[s][j][0]*ZUNSCALE, accq[s][j][1]*ZUNSCALE);
            *(float2*)(out + oB) = make_float2(accq[s][j][2]*ZUNSCALE, accq[s][j][3]*ZUNSCALE);
            *(float2*)(out + khat_off + oA) = make_float2(acck[s][j][0]*ZUNSCALE, acck[s][j][1]*ZUNSCALE);
            *(float2*)(out + khat_off + oB) = make_float2(acck[s][j][2]*ZUNSCALE, acck[s][j][3]*ZUNSCALE);
        }
    }
}

extern "C" void kernel_launch(void* const* d_in, const int* in_sizes, int n_in,
                              void* d_out, int out_size) {
    const float* queries = (const float*)d_in[0];
    const float* keys    = (const float*)d_in[1];
    const float* freqs   = (const float*)d_in[2];
    const float* offsets = (const float*)d_in[3];
    const float* gains   = (const float*)d_in[4];
    const float* z       = (const float*)d_in[5];
    float* out = (float*)d_out;

    cudaFuncSetAttribute(spe_mma_main, cudaFuncAttributeMaxDynamicSharedMemorySize, SMEM_BYTES);

    spe_pre<<<512 + NANCH/128, 128>>>(z, freqs, offsets, gains);
    spe_mma_main<<<dim3(LL/MT, HH, BB), 256, SMEM_BYTES>>>(queries, keys, out);
}